// round 3
// baseline (speedup 1.0000x reference)
#include <cuda_runtime.h>
#include <cuda_bf16.h>

#define NROWS 8192
#define DX 128
#define DY 64
#define TILE 128
#define NT (NROWS / TILE)  /* 64 */
#define NPAIRS (NT * (NT + 1) / 2)  /* 2080 */
#define BK 16
#define PAD 132            /* floats per smem k-row: 16B-aligned, conflict-free STS */

// ---------------- scratch (device globals; no allocation at runtime) ----------
__device__ float g_sqx[NROWS];
__device__ float g_sqy[NROWS];
__device__ float g_rxp[NT][NROWS];   // partial row sums of KX; slot [k][i] owned by exactly one CTA
__device__ float g_ryp[NT][NROWS];
__device__ float g_s1p[NPAIRS];      // per-CTA S1 partials
__device__ float g_red[NT * 4];      // per-block {S2, SX, SY} partials from row_reduce

// ---------------- kernel 0: squared norms -------------------------------------
__global__ void sq_kernel(const float* __restrict__ x, const float* __restrict__ y) {
    int i = blockIdx.x * blockDim.x + threadIdx.x;
    if (i >= NROWS) return;
    const float4* xr = (const float4*)(x + (size_t)i * DX);
    float s = 0.f;
#pragma unroll
    for (int k = 0; k < DX / 4; k++) {
        float4 v = xr[k];
        s += v.x * v.x + v.y * v.y + v.z * v.z + v.w * v.w;
    }
    g_sqx[i] = s;
    const float4* yr = (const float4*)(y + (size_t)i * DY);
    float t = 0.f;
#pragma unroll
    for (int k = 0; k < DY / 4; k++) {
        float4 v = yr[k];
        t += v.x * v.x + v.y * v.y + v.z * v.z + v.w * v.w;
    }
    g_sqy[i] = t;
}

// ---------------- main fused kernel -------------------------------------------
// One Gram-accumulation phase: acc[m][n] += <row gi0+ty8+m , row gj0+tx8+n>
// over KTOT columns of `base` (leading dim LD). Smem staged [BK][PAD] k-major.
template <int LD, int KTOT>
__device__ __forceinline__ void gram_phase(
    const float* __restrict__ base, int gi0, int gj0, float (&acc)[8][8],
    float (*sI)[PAD], float (*sJ)[PAD], int tid, int ty8, int tx8) {
    const int NCH = KTOT / BK;
    // each thread loads 2 float4 per tile per chunk: 512 float4 / 256 threads
    int f0 = tid, f1 = tid + 256;
    int r0 = f0 & 127, q0 = f0 >> 7;   // q in {0,1}
    int r1 = f1 & 127, q1 = f1 >> 7;   // q in {2,3}
    const float* pi0 = base + (size_t)(gi0 + r0) * LD + q0 * 4;
    const float* pi1 = base + (size_t)(gi0 + r1) * LD + q1 * 4;
    const float* pj0 = base + (size_t)(gj0 + r0) * LD + q0 * 4;
    const float* pj1 = base + (size_t)(gj0 + r1) * LD + q1 * 4;

    float4 vI0 = *(const float4*)pi0;
    float4 vI1 = *(const float4*)pi1;
    float4 vJ0 = *(const float4*)pj0;
    float4 vJ1 = *(const float4*)pj1;

#pragma unroll 1
    for (int c = 0; c < NCH; c++) {
        __syncthreads();  // previous chunk's compute done before overwrite
        sI[q0 * 4 + 0][r0] = vI0.x; sI[q0 * 4 + 1][r0] = vI0.y;
        sI[q0 * 4 + 2][r0] = vI0.z; sI[q0 * 4 + 3][r0] = vI0.w;
        sI[q1 * 4 + 0][r1] = vI1.x; sI[q1 * 4 + 1][r1] = vI1.y;
        sI[q1 * 4 + 2][r1] = vI1.z; sI[q1 * 4 + 3][r1] = vI1.w;
        sJ[q0 * 4 + 0][r0] = vJ0.x; sJ[q0 * 4 + 1][r0] = vJ0.y;
        sJ[q0 * 4 + 2][r0] = vJ0.z; sJ[q0 * 4 + 3][r0] = vJ0.w;
        sJ[q1 * 4 + 0][r1] = vJ1.x; sJ[q1 * 4 + 1][r1] = vJ1.y;
        sJ[q1 * 4 + 2][r1] = vJ1.z; sJ[q1 * 4 + 3][r1] = vJ1.w;
        __syncthreads();
        if (c + 1 < NCH) {  // prefetch next chunk; overlaps compute below
            int kb = (c + 1) * BK;
            vI0 = *(const float4*)(pi0 + kb);
            vI1 = *(const float4*)(pi1 + kb);
            vJ0 = *(const float4*)(pj0 + kb);
            vJ1 = *(const float4*)(pj1 + kb);
        }
#pragma unroll
        for (int kk = 0; kk < BK; kk++) {
            float av[8], bv[8];
#pragma unroll
            for (int m = 0; m < 8; m++) av[m] = sI[kk][ty8 + m];
#pragma unroll
            for (int n = 0; n < 8; n++) bv[n] = sJ[kk][tx8 + n];
#pragma unroll
            for (int m = 0; m < 8; m++)
#pragma unroll
                for (int n = 0; n < 8; n++)
                    acc[m][n] = fmaf(av[m], bv[n], acc[m][n]);
        }
    }
}

__global__ __launch_bounds__(256) void hsic_main(const float* __restrict__ x,
                                                 const float* __restrict__ y) {
    __shared__ float sI[BK][PAD];
    __shared__ float sJ[BK][PAD];
    __shared__ float sred[16][TILE];

    // unrank linear pair id -> (a, b) with a <= b (upper triangle, row-major)
    const int p = blockIdx.x;
    int a = 0, rowstart = 0;
#pragma unroll 1
    while (a < NT - 1 && rowstart + (NT - a) <= p) {
        rowstart += NT - a;
        a++;
    }
    int b = p - rowstart + a;
    if (b >= NT) b = NT - 1;  // defensive clamp (unreachable for valid p)

    const int tid = threadIdx.x;
    const int tx = tid & 15, ty = tid >> 4;
    const int tx8 = tx * 8, ty8 = ty * 8;
    const int gi0 = a * TILE, gj0 = b * TILE;
    const bool diag = (a == b);

    float accX[8][8], accY[8][8];
#pragma unroll
    for (int m = 0; m < 8; m++)
#pragma unroll
        for (int n = 0; n < 8; n++) { accX[m][n] = 0.f; accY[m][n] = 0.f; }

    gram_phase<DX, DX>(x, gi0, gj0, accX, sI, sJ, tid, ty8, tx8);
    gram_phase<DY, DY>(y, gi0, gj0, accY, sI, sJ, tid, ty8, tx8);

    // ---- epilogue: dist -> exp -> partial sums ----
    float sqxi[8], sqyi[8], sqxj[8], sqyj[8];
#pragma unroll
    for (int m = 0; m < 8; m++) {
        sqxi[m] = g_sqx[gi0 + ty8 + m];
        sqyi[m] = g_sqy[gi0 + ty8 + m];
    }
#pragma unroll
    for (int n = 0; n < 8; n++) {
        sqxj[n] = g_sqx[gj0 + tx8 + n];
        sqyj[n] = g_sqy[gj0 + tx8 + n];
    }

    float s1 = 0.f;
    float rwx[8], rwy[8], clx[8], cly[8];
#pragma unroll
    for (int m = 0; m < 8; m++) { rwx[m] = 0.f; rwy[m] = 0.f; clx[m] = 0.f; cly[m] = 0.f; }

#pragma unroll
    for (int m = 0; m < 8; m++)
#pragma unroll
        for (int n = 0; n < 8; n++) {
            float dx = sqxi[m] + sqxj[n] - 2.f * accX[m][n];
            float dy = sqyi[m] + sqyj[n] - 2.f * accY[m][n];
            float ex = __expf(-0.5f * dx);
            float ey = __expf(-0.5f * dy);
            s1 = fmaf(ex, ey, s1);
            rwx[m] += ex; clx[n] += ex;
            rwy[m] += ey; cly[n] += ey;
        }

    // ---- deterministic in-block reductions via sred ----
    // rows of tile a (sum over j in tile b) -> g_rxp[b][gi0+r]
#pragma unroll
    for (int m = 0; m < 8; m++) sred[tx][ty8 + m] = rwx[m];
    __syncthreads();
    if (tid < TILE) {
        float s = 0.f;
#pragma unroll
        for (int t = 0; t < 16; t++) s += sred[t][tid];
        g_rxp[b][gi0 + tid] = s;
    }
    __syncthreads();
#pragma unroll
    for (int m = 0; m < 8; m++) sred[tx][ty8 + m] = rwy[m];
    __syncthreads();
    if (tid < TILE) {
        float s = 0.f;
#pragma unroll
        for (int t = 0; t < 16; t++) s += sred[t][tid];
        g_ryp[b][gi0 + tid] = s;
    }
    __syncthreads();

    if (!diag) {  // columns of tile b (sum over i in tile a) -> g_rxp[a][gj0+c]
#pragma unroll
        for (int n = 0; n < 8; n++) sred[ty][tx8 + n] = clx[n];
        __syncthreads();
        if (tid < TILE) {
            float s = 0.f;
#pragma unroll
            for (int t = 0; t < 16; t++) s += sred[t][tid];
            g_rxp[a][gj0 + tid] = s;
        }
        __syncthreads();
#pragma unroll
        for (int n = 0; n < 8; n++) sred[ty][tx8 + n] = cly[n];
        __syncthreads();
        if (tid < TILE) {
            float s = 0.f;
#pragma unroll
            for (int t = 0; t < 16; t++) s += sred[t][tid];
            g_ryp[a][gj0 + tid] = s;
        }
        __syncthreads();
    }

    // ---- S1 tree reduce (deterministic pairing) ----
    float* fr = &sred[0][0];
    fr[tid] = s1;
    __syncthreads();
#pragma unroll
    for (int off = 128; off > 0; off >>= 1) {
        if (tid < off) fr[tid] += fr[tid + off];
        __syncthreads();
    }
    if (tid == 0) g_s1p[p] = (diag ? 1.f : 2.f) * fr[0];
}

// ---------------- kernel 2: combine row-sum partials --------------------------
__global__ void row_reduce_kernel() {
    int t = threadIdx.x;
    int i = blockIdx.x * 128 + t;
    float rx = 0.f, ry = 0.f;
#pragma unroll
    for (int k = 0; k < NT; k++) {
        rx += g_rxp[k][i];
        ry += g_ryp[k][i];
    }
    __shared__ float s2s[128], sxs[128], sys[128];
    s2s[t] = rx * ry; sxs[t] = rx; sys[t] = ry;
    __syncthreads();
#pragma unroll
    for (int off = 64; off > 0; off >>= 1) {
        if (t < off) {
            s2s[t] += s2s[t + off];
            sxs[t] += sxs[t + off];
            sys[t] += sys[t + off];
        }
        __syncthreads();
    }
    if (t == 0) {
        g_red[blockIdx.x * 4 + 0] = s2s[0];
        g_red[blockIdx.x * 4 + 1] = sxs[0];
        g_red[blockIdx.x * 4 + 2] = sys[0];
    }
}

// ---------------- kernel 3: finalize ------------------------------------------
__global__ void finalize_kernel(float* __restrict__ out) {
    __shared__ float buf[256];
    int t = threadIdx.x;
    float s = 0.f;
    for (int i = t; i < NPAIRS; i += 256) s += g_s1p[i];
    buf[t] = s;
    __syncthreads();
#pragma unroll
    for (int off = 128; off > 0; off >>= 1) {
        if (t < off) buf[t] += buf[t + off];
        __syncthreads();
    }
    if (t == 0) {
        float S1 = buf[0], S2 = 0.f, SX = 0.f, SY = 0.f;
        for (int k = 0; k < NT; k++) {
            S2 += g_red[4 * k + 0];
            SX += g_red[4 * k + 1];
            SY += g_red[4 * k + 2];
        }
        const float invN = 1.f / (float)NROWS;
        out[0] = S1 - 2.f * S2 * invN + SX * SY * invN * invN;
    }
}

// ---------------- entry --------------------------------------------------------
extern "C" void kernel_launch(void* const* d_in, const int* in_sizes, int n_in,
                              void* d_out, int out_size) {
    const float* x = (const float*)d_in[0];
    const float* y = (const float*)d_in[1];
    if (n_in >= 2 && in_sizes[0] == NROWS * DY && in_sizes[1] == NROWS * DX) {
        const float* tmp = x; x = y; y = tmp;  // defensive: metadata order flipped
    }
    float* out = (float*)d_out;

    sq_kernel<<<NROWS / 256, 256>>>(x, y);
    hsic_main<<<NPAIRS, 256>>>(x, y);
    row_reduce_kernel<<<NT, 128>>>();
    finalize_kernel<<<1, 256>>>(out);
}

// round 5
// speedup vs baseline: 3.8937x; 3.8937x over previous
#include <cuda_runtime.h>
#include <cuda_bf16.h>
#include <cstdint>

#define NROWS 8192
#define DX 128
#define DY 64
#define TILE 128
#define NT 64                      /* NROWS / TILE */
#define NPAIRS (NT * (NT + 1) / 2) /* 2080 */

#define LDAX 136   /* padded bf16 row stride for X tiles (272 B) */
#define LDAY 72    /* padded bf16 row stride for Y tiles (144 B) */

#define XT_BYTES (128 * LDAX * 2)  /* 34816 */
#define YT_BYTES (128 * LDAY * 2)  /* 18432 */
#define DYN_SMEM (2 * XT_BYTES + 2 * YT_BYTES) /* 106496 */

// ---------------- scratch (device globals; no allocation at runtime) ----------
__device__ __align__(16) __nv_bfloat16 g_xb[NROWS * DX];
__device__ __align__(16) __nv_bfloat16 g_yb[NROWS * DY];
__device__ float g_sqx[NROWS];
__device__ float g_sqy[NROWS];
__device__ float g_rxp[NT][NROWS];
__device__ float g_ryp[NT][NROWS];
__device__ float g_s1p[NPAIRS];
__device__ float g_red[NT * 4];

// ---------------- PTX helpers --------------------------------------------------
__device__ __forceinline__ uint32_t smem_u32(const void* p) {
    uint32_t a;
    asm("{ .reg .u64 t; cvta.to.shared.u64 t, %1; cvt.u32.u64 %0, t; }" : "=r"(a) : "l"(p));
    return a;
}
#define LDSM4(r0, r1, r2, r3, addr) \
    asm volatile("ldmatrix.sync.aligned.m8n8.x4.shared.b16 {%0,%1,%2,%3}, [%4];" \
                 : "=r"(r0), "=r"(r1), "=r"(r2), "=r"(r3) : "r"(addr))
#define MMA16816(d, a, b0v, b1v) \
    asm volatile("mma.sync.aligned.m16n8k16.row.col.f32.bf16.bf16.f32 " \
                 "{%0,%1,%2,%3}, {%4,%5,%6,%7}, {%8,%9}, {%0,%1,%2,%3};" \
                 : "+f"((d)[0]), "+f"((d)[1]), "+f"((d)[2]), "+f"((d)[3]) \
                 : "r"((a)[0]), "r"((a)[1]), "r"((a)[2]), "r"((a)[3]), \
                   "r"(b0v), "r"(b1v))

// ---------------- kernel 0: bf16 quantize + squared norms ---------------------
__global__ void prep_kernel(const float* __restrict__ x, const float* __restrict__ y) {
    int gw = blockIdx.x * 8 + (threadIdx.x >> 5);  // one warp per row
    int lane = threadIdx.x & 31;
    const float* xr = x + (size_t)gw * DX;
    float s = 0.f;
#pragma unroll
    for (int q = 0; q < 4; q++) {
        int c = lane + 32 * q;
        __nv_bfloat16 b = __float2bfloat16(xr[c]);
        g_xb[(size_t)gw * DX + c] = b;
        float f = __bfloat162float(b);
        s = fmaf(f, f, s);
    }
#pragma unroll
    for (int o = 16; o > 0; o >>= 1) s += __shfl_xor_sync(0xFFFFFFFFu, s, o);
    if (lane == 0) g_sqx[gw] = s;

    const float* yr = y + (size_t)gw * DY;
    float t = 0.f;
#pragma unroll
    for (int q = 0; q < 2; q++) {
        int c = lane + 32 * q;
        __nv_bfloat16 b = __float2bfloat16(yr[c]);
        g_yb[(size_t)gw * DY + c] = b;
        float f = __bfloat162float(b);
        t = fmaf(f, f, t);
    }
#pragma unroll
    for (int o = 16; o > 0; o >>= 1) t += __shfl_xor_sync(0xFFFFFFFFu, t, o);
    if (lane == 0) g_sqy[gw] = t;
}

// ---------------- main fused kernel (mma.sync bf16) ----------------------------
__global__ __launch_bounds__(512) void hsic_main() {
    extern __shared__ char dynsmem[];
    __nv_bfloat16* sXa = (__nv_bfloat16*)dynsmem;
    __nv_bfloat16* sXb = (__nv_bfloat16*)(dynsmem + XT_BYTES);
    __nv_bfloat16* sYa = (__nv_bfloat16*)(dynsmem + 2 * XT_BYTES);
    __nv_bfloat16* sYb = (__nv_bfloat16*)(dynsmem + 2 * XT_BYTES + YT_BYTES);

    __shared__ float srowX[4][128], srowY[4][128];
    __shared__ float scolX[4][128], scolY[4][128];
    __shared__ float hsqxi[128], hsqxj[128], hsqyi[128], hsqyj[128];
    __shared__ float s1buf[512];

    // unrank pair id -> (a, b), a <= b
    const int p = blockIdx.x;
    int a = 0, rowstart = 0;
#pragma unroll 1
    while (a < NT - 1 && rowstart + (NT - a) <= p) { rowstart += NT - a; a++; }
    int b = p - rowstart + a;
    if (b >= NT) b = NT - 1;

    const int tid = threadIdx.x;
    const int gi0 = a * TILE, gj0 = b * TILE;
    const bool diag = (a == b);

    // ---- stage tiles into padded smem ----
#pragma unroll
    for (int it = 0; it < 4; it++) {  // X tiles: 2048 uint4 each
        int f = tid + 512 * it;
        int row = f >> 4, cc = f & 15;
        uint32_t off = (uint32_t)row * LDAX + cc * 8;
        *(uint4*)(sXa + off) = *(const uint4*)(g_xb + ((size_t)(gi0 + row) * DX + cc * 8));
        *(uint4*)(sXb + off) = *(const uint4*)(g_xb + ((size_t)(gj0 + row) * DX + cc * 8));
    }
#pragma unroll
    for (int it = 0; it < 2; it++) {  // Y tiles: 1024 uint4 each
        int f = tid + 512 * it;
        int row = f >> 3, cc = f & 7;
        uint32_t off = (uint32_t)row * LDAY + cc * 8;
        *(uint4*)(sYa + off) = *(const uint4*)(g_yb + ((size_t)(gi0 + row) * DY + cc * 8));
        *(uint4*)(sYb + off) = *(const uint4*)(g_yb + ((size_t)(gj0 + row) * DY + cc * 8));
    }
    if (tid < 128) {  // half-norms
        hsqxi[tid] = 0.5f * g_sqx[gi0 + tid];
        hsqxj[tid] = 0.5f * g_sqx[gj0 + tid];
        hsqyi[tid] = 0.5f * g_sqy[gi0 + tid];
        hsqyj[tid] = 0.5f * g_sqy[gj0 + tid];
    }
    __syncthreads();

    // ---- warp setup: 16 warps, 4x4 grid of 32x32 warp tiles ----
    const int w = tid >> 5, lane = tid & 31;
    const int wm = w & 3, wn = w >> 2;
    const int m0 = wm * 32, n0 = wn * 32;
    const int l15 = lane & 15, lhi = (lane >> 4) << 3;  // ldmatrix row / k-half

    const uint32_t aXb = smem_u32(sXa) + ((uint32_t)(m0 + l15) * LDAX + lhi) * 2;
    const uint32_t bXb = smem_u32(sXb) + ((uint32_t)(n0 + l15) * LDAX + lhi) * 2;
    const uint32_t aYb = smem_u32(sYa) + ((uint32_t)(m0 + l15) * LDAY + lhi) * 2;
    const uint32_t bYb = smem_u32(sYb) + ((uint32_t)(n0 + l15) * LDAY + lhi) * 2;

    float accX[2][4][4], accY[2][4][4];
#pragma unroll
    for (int mi = 0; mi < 2; mi++)
#pragma unroll
        for (int ni = 0; ni < 4; ni++)
#pragma unroll
            for (int e = 0; e < 4; e++) { accX[mi][ni][e] = 0.f; accY[mi][ni][e] = 0.f; }

    // ---- X mainloop: K=128, 8 chunks of k16 ----
#pragma unroll
    for (int kc = 0; kc < 8; kc++) {
        uint32_t a0[4], a1[4], b0[4], b1[4];
        LDSM4(a0[0], a0[1], a0[2], a0[3], aXb + kc * 32);
        LDSM4(a1[0], a1[1], a1[2], a1[3], aXb + 16 * LDAX * 2 + kc * 32);
        LDSM4(b0[0], b0[1], b0[2], b0[3], bXb + kc * 32);
        LDSM4(b1[0], b1[1], b1[2], b1[3], bXb + 16 * LDAX * 2 + kc * 32);
#pragma unroll
        for (int mi = 0; mi < 2; mi++) {
            uint32_t* av = mi ? a1 : a0;
            MMA16816(accX[mi][0], av, b0[0], b0[2]);
            MMA16816(accX[mi][1], av, b0[1], b0[3]);
            MMA16816(accX[mi][2], av, b1[0], b1[2]);
            MMA16816(accX[mi][3], av, b1[1], b1[3]);
        }
    }
    // ---- Y mainloop: K=64, 4 chunks ----
#pragma unroll
    for (int kc = 0; kc < 4; kc++) {
        uint32_t a0[4], a1[4], b0[4], b1[4];
        LDSM4(a0[0], a0[1], a0[2], a0[3], aYb + kc * 32);
        LDSM4(a1[0], a1[1], a1[2], a1[3], aYb + 16 * LDAY * 2 + kc * 32);
        LDSM4(b0[0], b0[1], b0[2], b0[3], bYb + kc * 32);
        LDSM4(b1[0], b1[1], b1[2], b1[3], bYb + 16 * LDAY * 2 + kc * 32);
#pragma unroll
        for (int mi = 0; mi < 2; mi++) {
            uint32_t* av = mi ? a1 : a0;
            MMA16816(accY[mi][0], av, b0[0], b0[2]);
            MMA16816(accY[mi][1], av, b0[1], b0[3]);
            MMA16816(accY[mi][2], av, b1[0], b1[2]);
            MMA16816(accY[mi][3], av, b1[1], b1[3]);
        }
    }

    // ---- epilogue: exp + partial sums on fragments ----
    const int t4 = lane & 3, t28 = lane >> 2;
    float rwx[2][2], rwy[2][2];
    float cwx[4][2], cwy[4][2];
#pragma unroll
    for (int mi = 0; mi < 2; mi++)
#pragma unroll
        for (int rr = 0; rr < 2; rr++) { rwx[mi][rr] = 0.f; rwy[mi][rr] = 0.f; }
#pragma unroll
    for (int ni = 0; ni < 4; ni++)
#pragma unroll
        for (int cp = 0; cp < 2; cp++) { cwx[ni][cp] = 0.f; cwy[ni][cp] = 0.f; }
    float s1 = 0.f;

#pragma unroll
    for (int mi = 0; mi < 2; mi++) {
        const int r0 = m0 + mi * 16 + t28;
        const float hx0 = hsqxi[r0], hx1 = hsqxi[r0 + 8];
        const float hy0 = hsqyi[r0], hy1 = hsqyi[r0 + 8];
#pragma unroll
        for (int ni = 0; ni < 4; ni++) {
            const int c0 = n0 + ni * 8 + 2 * t4;
            const float hxj0 = hsqxj[c0], hxj1 = hsqxj[c0 + 1];
            const float hyj0 = hsqyj[c0], hyj1 = hsqyj[c0 + 1];
            float ex00 = __expf(accX[mi][ni][0] - hx0 - hxj0);
            float ex01 = __expf(accX[mi][ni][1] - hx0 - hxj1);
            float ex10 = __expf(accX[mi][ni][2] - hx1 - hxj0);
            float ex11 = __expf(accX[mi][ni][3] - hx1 - hxj1);
            float ey00 = __expf(accY[mi][ni][0] - hy0 - hyj0);
            float ey01 = __expf(accY[mi][ni][1] - hy0 - hyj1);
            float ey10 = __expf(accY[mi][ni][2] - hy1 - hyj0);
            float ey11 = __expf(accY[mi][ni][3] - hy1 - hyj1);
            s1 = fmaf(ex00, ey00, s1);
            s1 = fmaf(ex01, ey01, s1);
            s1 = fmaf(ex10, ey10, s1);
            s1 = fmaf(ex11, ey11, s1);
            rwx[mi][0] += ex00 + ex01; rwx[mi][1] += ex10 + ex11;
            rwy[mi][0] += ey00 + ey01; rwy[mi][1] += ey10 + ey11;
            cwx[ni][0] += ex00 + ex10; cwx[ni][1] += ex01 + ex11;
            cwy[ni][0] += ey00 + ey10; cwy[ni][1] += ey01 + ey11;
        }
    }

    // row sums: reduce over t4 (lanes xor 1,2)
#pragma unroll
    for (int mi = 0; mi < 2; mi++)
#pragma unroll
        for (int rr = 0; rr < 2; rr++) {
            float vx = rwx[mi][rr], vy = rwy[mi][rr];
            vx += __shfl_xor_sync(0xFFFFFFFFu, vx, 1);
            vx += __shfl_xor_sync(0xFFFFFFFFu, vx, 2);
            vy += __shfl_xor_sync(0xFFFFFFFFu, vy, 1);
            vy += __shfl_xor_sync(0xFFFFFFFFu, vy, 2);
            if (t4 == 0) {
                srowX[wn][m0 + mi * 16 + rr * 8 + t28] = vx;
                srowY[wn][m0 + mi * 16 + rr * 8 + t28] = vy;
            }
        }
    // col sums: reduce over t28 (lanes xor 4,8,16)
#pragma unroll
    for (int ni = 0; ni < 4; ni++)
#pragma unroll
        for (int cp = 0; cp < 2; cp++) {
            float vx = cwx[ni][cp], vy = cwy[ni][cp];
            vx += __shfl_xor_sync(0xFFFFFFFFu, vx, 4);
            vx += __shfl_xor_sync(0xFFFFFFFFu, vx, 8);
            vx += __shfl_xor_sync(0xFFFFFFFFu, vx, 16);
            vy += __shfl_xor_sync(0xFFFFFFFFu, vy, 4);
            vy += __shfl_xor_sync(0xFFFFFFFFu, vy, 8);
            vy += __shfl_xor_sync(0xFFFFFFFFu, vy, 16);
            if (t28 == 0) {
                scolX[wm][n0 + ni * 8 + 2 * t4 + cp] = vx;
                scolY[wm][n0 + ni * 8 + 2 * t4 + cp] = vy;
            }
        }
    s1buf[tid] = s1;
    __syncthreads();

    if (tid < 128) {
        g_rxp[b][gi0 + tid] = srowX[0][tid] + srowX[1][tid] + srowX[2][tid] + srowX[3][tid];
        g_ryp[b][gi0 + tid] = srowY[0][tid] + srowY[1][tid] + srowY[2][tid] + srowY[3][tid];
        if (!diag) {
            g_rxp[a][gj0 + tid] = scolX[0][tid] + scolX[1][tid] + scolX[2][tid] + scolX[3][tid];
            g_ryp[a][gj0 + tid] = scolY[0][tid] + scolY[1][tid] + scolY[2][tid] + scolY[3][tid];
        }
    }
#pragma unroll
    for (int off = 256; off > 0; off >>= 1) {
        if (tid < off) s1buf[tid] += s1buf[tid + off];
        __syncthreads();
    }
    if (tid == 0) g_s1p[p] = (diag ? 1.f : 2.f) * s1buf[0];
}

// ---------------- kernel 2: combine row-sum partials --------------------------
__global__ void row_reduce_kernel() {
    int t = threadIdx.x;
    int i = blockIdx.x * 128 + t;
    float rx = 0.f, ry = 0.f;
#pragma unroll
    for (int k = 0; k < NT; k++) {
        rx += g_rxp[k][i];
        ry += g_ryp[k][i];
    }
    __shared__ float s2s[128], sxs[128], sys[128];
    s2s[t] = rx * ry; sxs[t] = rx; sys[t] = ry;
    __syncthreads();
#pragma unroll
    for (int off = 64; off > 0; off >>= 1) {
        if (t < off) {
            s2s[t] += s2s[t + off];
            sxs[t] += sxs[t + off];
            sys[t] += sys[t + off];
        }
        __syncthreads();
    }
    if (t == 0) {
        g_red[blockIdx.x * 4 + 0] = s2s[0];
        g_red[blockIdx.x * 4 + 1] = sxs[0];
        g_red[blockIdx.x * 4 + 2] = sys[0];
    }
}

// ---------------- kernel 3: finalize ------------------------------------------
__global__ void finalize_kernel(float* __restrict__ out) {
    __shared__ float buf[256];
    int t = threadIdx.x;
    float s = 0.f;
    for (int i = t; i < NPAIRS; i += 256) s += g_s1p[i];
    buf[t] = s;
    __syncthreads();
#pragma unroll
    for (int off = 128; off > 0; off >>= 1) {
        if (t < off) buf[t] += buf[t + off];
        __syncthreads();
    }
    if (t == 0) {
        float S1 = buf[0], S2 = 0.f, SX = 0.f, SY = 0.f;
        for (int k = 0; k < NT; k++) {
            S2 += g_red[4 * k + 0];
            SX += g_red[4 * k + 1];
            SY += g_red[4 * k + 2];
        }
        const float invN = 1.f / (float)NROWS;
        out[0] = S1 - 2.f * S2 * invN + SX * SY * invN * invN;
    }
}

// ---------------- entry --------------------------------------------------------
extern "C" void kernel_launch(void* const* d_in, const int* in_sizes, int n_in,
                              void* d_out, int out_size) {
    const float* x = (const float*)d_in[0];
    const float* y = (const float*)d_in[1];
    if (n_in >= 2 && in_sizes[0] == NROWS * DY && in_sizes[1] == NROWS * DX) {
        const float* tmp = x; x = y; y = tmp;
    }
    float* out = (float*)d_out;

    cudaFuncSetAttribute(hsic_main, cudaFuncAttributeMaxDynamicSharedMemorySize, DYN_SMEM);

    prep_kernel<<<NROWS / 8, 256>>>(x, y);
    hsic_main<<<NPAIRS, 512, DYN_SMEM>>>();
    row_reduce_kernel<<<NT, 128>>>();
    finalize_kernel<<<1, 256>>>(out);
}